// round 1
// baseline (speedup 1.0000x reference)
#include <cuda_runtime.h>
#include <cstdint>

// Problem constants (fixed by the reference)
#define NN 32
#define CC 64
#define PP 4096                 // H*W
#define SS 512
#define NPIX (NN * PP)          // 131072 pixels
#define TOTAL (NN * CC * PP)    // 8388608 elements

#define BN 128                  // codes per shared tile
#define PITCH (BN + 4)          // float pitch; %4==0 for 16B-aligned LDS128, +4 breaks worst STS conflicts

// ---------------- device scratch (no allocations allowed) ----------------
__device__ __align__(16) float g_c2[SS];
__device__ int g_idx[NPIX];
__device__ unsigned long long g_loss_acc;

// ---------------- f32x2 packed helpers (Blackwell) ----------------
__device__ __forceinline__ unsigned long long pack2(float v) {
    unsigned long long r;
    unsigned u = __float_as_uint(v);
    asm("mov.b64 %0, {%1, %1};" : "=l"(r) : "r"(u));
    return r;
}
__device__ __forceinline__ unsigned long long fma2(unsigned long long a,
                                                   unsigned long long b,
                                                   unsigned long long c) {
    unsigned long long d;
    asm("fma.rn.f32x2 %0, %1, %2, %3;" : "=l"(d) : "l"(a), "l"(b), "l"(c));
    return d;
}
__device__ __forceinline__ unsigned long long add2(unsigned long long a,
                                                   unsigned long long b) {
    unsigned long long d;
    asm("add.rn.f32x2 %0, %1, %2;" : "=l"(d) : "l"(a), "l"(b));
    return d;
}
__device__ __forceinline__ void unpack2(unsigned long long v, float& lo, float& hi) {
    unsigned a, b;
    asm("mov.b64 {%0, %1}, %2;" : "=r"(a), "=r"(b) : "l"(v));
    lo = __uint_as_float(a);
    hi = __uint_as_float(b);
}

// ---------------- kernel A: codebook row norms + zero loss accumulator ----------------
__global__ void prep_kernel(const float* __restrict__ cb) {
    int s = threadIdx.x;
    if (s == 0) g_loss_acc = 0ull;
    if (s < SS) {
        float acc = 0.f;
#pragma unroll
        for (int c = 0; c < CC; ++c) {
            float v = cb[s * CC + c];
            acc = fmaf(v, v, acc);
        }
        g_c2[s] = acc;
    }
}

// ---------------- kernel B: per-pixel argmin over 512 codes ----------------
// Thread = one pixel. x row (64 floats) cached in registers; codebook tiled
// (transposed) in shared; inner product via packed f32x2 FMAs, 16 codes per
// register group (8 packed accumulators).
__global__ void __launch_bounds__(256) argmin_kernel(const float* __restrict__ x,
                                                     const float* __restrict__ cb) {
    __shared__ __align__(16) float sh[CC * PITCH];

    const int q = blockIdx.x * 256 + threadIdx.x;   // pixel id, grid covers exactly
    const int n = q >> 12;                          // q / PP
    const int p = q & (PP - 1);
    const float* xb = x + (size_t)n * CC * PP + p;

    // Load this pixel's feature vector and ||x||^2 (fp32, sequential order)
    float xr[CC];
    float x2 = 0.f;
#pragma unroll
    for (int c = 0; c < CC; ++c) {
        float v = xb[(size_t)c * PP];
        xr[c] = v;
        x2 = fmaf(v, v, x2);
    }
    const unsigned long long x2d = pack2(x2);
    const unsigned long long m2d = pack2(-2.0f);

    float best = 3.4e38f;
    int bidx = 0;

    for (int s0 = 0; s0 < SS; s0 += BN) {
        __syncthreads();
        // Load + transpose codebook tile: sh[c][s'] = cb[s0+s'][c]
        for (int e = threadIdx.x; e < BN * CC; e += 256) {
            int sp = e >> 6;     // e / 64
            int c = e & 63;
            sh[c * PITCH + sp] = cb[(s0 + sp) * CC + c];
        }
        __syncthreads();

        for (int g = 0; g < BN; g += 16) {
            unsigned long long acc[8];
#pragma unroll
            for (int j = 0; j < 8; ++j) acc[j] = 0ull;   // packed (0,0)

#pragma unroll
            for (int c = 0; c < CC; ++c) {
                unsigned long long xd = pack2(xr[c]);
                const ulonglong2* rp =
                    reinterpret_cast<const ulonglong2*>(&sh[c * PITCH + g]);
                ulonglong2 r0 = rp[0];   // codes g+0..g+3  (2 packed pairs)
                ulonglong2 r1 = rp[1];   // codes g+4..g+7
                ulonglong2 r2 = rp[2];   // codes g+8..g+11
                ulonglong2 r3 = rp[3];   // codes g+12..g+15
                acc[0] = fma2(xd, r0.x, acc[0]);
                acc[1] = fma2(xd, r0.y, acc[1]);
                acc[2] = fma2(xd, r1.x, acc[2]);
                acc[3] = fma2(xd, r1.y, acc[3]);
                acc[4] = fma2(xd, r2.x, acc[4]);
                acc[5] = fma2(xd, r2.y, acc[5]);
                acc[6] = fma2(xd, r3.x, acc[6]);
                acc[7] = fma2(xd, r3.y, acc[7]);
            }

            // dist = fl(fl(x2 + c2) - 2*cross); compare ascending s (first-min wins)
#pragma unroll
            for (int j = 0; j < 8; ++j) {
                int s = s0 + g + 2 * j;
                unsigned long long c2p =
                    *reinterpret_cast<const unsigned long long*>(&g_c2[s]);
                unsigned long long t1 = add2(x2d, c2p);
                unsigned long long d = fma2(acc[j], m2d, t1);
                float dlo, dhi;
                unpack2(d, dlo, dhi);
                if (dlo < best) { best = dlo; bidx = s; }
                if (dhi < best) { best = dhi; bidx = s + 1; }
            }
        }
    }
    g_idx[q] = bidx;
}

// ---------------- kernel C: gather, straight-through output, loss partials ----------------
// Output layout (fp32): [0]=loss_codebook, [1]=loss_commitment,
// [2 .. 2+NPIX) = indices (as float), [2+NPIX ..) = out (N,C,H,W)
__global__ void __launch_bounds__(256) gather_kernel(const float* __restrict__ x,
                                                     const float* __restrict__ cb,
                                                     float* __restrict__ out) {
    const int q = blockIdx.x * 256 + threadIdx.x;
    const int n = q >> 12;
    const int p = q & (PP - 1);
    const int idx = g_idx[q];

    out[2 + q] = (float)idx;    // indices region, row-major (n, h, w) == n*PP + p

    const float* xb = x + (size_t)n * CC * PP + p;
    float* ob = out + 2 + NPIX + (size_t)n * CC * PP + p;
    const float4* crow = reinterpret_cast<const float4*>(cb + (size_t)idx * CC);

    float lsum = 0.f;
#pragma unroll
    for (int c4 = 0; c4 < CC / 4; ++c4) {
        float4 cv = crow[c4];
        float cvv[4] = {cv.x, cv.y, cv.z, cv.w};
#pragma unroll
        for (int i = 0; i < 4; ++i) {
            int c = c4 * 4 + i;
            float xv = xb[(size_t)c * PP];
            float xq = cvv[i];
            float d = xq - xv;          // stop_grad(x_q - x), reference rounding
            ob[(size_t)c * PP] = xv + d;
            float dd = xv - xq;
            lsum = fmaf(dd, dd, lsum);
        }
    }

    // Deterministic fixed-point reduction (scale 2^32)
    double dsum = (double)lsum;
#pragma unroll
    for (int off = 16; off; off >>= 1)
        dsum += __shfl_down_sync(0xffffffffu, dsum, off);

    __shared__ double wsum[8];
    if ((threadIdx.x & 31) == 0) wsum[threadIdx.x >> 5] = dsum;
    __syncthreads();
    if (threadIdx.x == 0) {
        double t = 0.0;
#pragma unroll
        for (int w = 0; w < 8; ++w) t += wsum[w];
        long long fx = __double2ll_rn(t * 4294967296.0);
        atomicAdd(&g_loss_acc, (unsigned long long)fx);
    }
}

// ---------------- kernel D: finalize losses ----------------
__global__ void finish_kernel(float* __restrict__ out) {
    double s = (double)g_loss_acc * (1.0 / 4294967296.0);
    float loss = (float)(s / (double)TOTAL);
    out[0] = loss;   // loss_codebook
    out[1] = loss;   // loss_commitment (numerically identical)
}

// ---------------- launch ----------------
extern "C" void kernel_launch(void* const* d_in, const int* in_sizes, int n_in,
                              void* d_out, int out_size) {
    const float* x = (const float*)d_in[0];
    const float* cb = (const float*)d_in[1];
    // Defensive: identify tensors by size if ordering differs
    if (n_in >= 2 && in_sizes[0] == SS * CC && in_sizes[1] == TOTAL) {
        const float* t = x; x = cb; cb = t;
    }
    float* out = (float*)d_out;

    prep_kernel<<<1, 512>>>(cb);
    argmin_kernel<<<NPIX / 256, 256>>>(x, cb);
    gather_kernel<<<NPIX / 256, 256>>>(x, cb, out);
    finish_kernel<<<1, 1>>>(out);
}

// round 3
// speedup vs baseline: 1.3249x; 1.3249x over previous
#include <cuda_runtime.h>
#include <cstdint>

// Problem constants (fixed by the reference)
#define NN 32
#define CC 64
#define PP 4096                 // H*W
#define SS 512
#define NPIX (NN * PP)          // 131072 pixels
#define TOTAL (NN * CC * PP)    // 8388608 elements

// Argmin kernel tiling
#define TPB 128                 // threads per block
#define PXB 256                 // pixels per block
#define PXT 2                   // pixels per thread
#define CBT 128                 // codes staged per smem tile
#define GRP 32                  // codes per register group (16 packed pairs)
#define CBP 132                 // cb smem pitch in floats (132*4 % 16 == 0 -> aligned LDS.128)

#define SX_FLOATS (CC * PXB)            // 16384
#define SCB_FLOATS (CC * CBP)           // 8448
#define SMEM_FLOATS (SX_FLOATS + SCB_FLOATS + SS + 16)
#define SMEM_BYTES (SMEM_FLOATS * 4)    // ~101.4 KB -> 2 blocks/SM

// ---------------- device scratch (no allocations allowed) ----------------
__device__ __align__(16) float g_c2[SS];
__device__ unsigned long long g_loss_acc;

// ---------------- f32x2 packed helpers (Blackwell) ----------------
typedef unsigned long long ull;

__device__ __forceinline__ ull pack2(float v) {
    ull r;
    unsigned u = __float_as_uint(v);
    asm("mov.b64 %0, {%1, %1};" : "=l"(r) : "r"(u));
    return r;
}
__device__ __forceinline__ ull fma2(ull a, ull b, ull c) {
    ull d;
    asm("fma.rn.f32x2 %0, %1, %2, %3;" : "=l"(d) : "l"(a), "l"(b), "l"(c));
    return d;
}
__device__ __forceinline__ ull add2(ull a, ull b) {
    ull d;
    asm("add.rn.f32x2 %0, %1, %2;" : "=l"(d) : "l"(a), "l"(b));
    return d;
}
__device__ __forceinline__ void unpack2(ull v, float& lo, float& hi) {
    unsigned a, b;
    asm("mov.b64 {%0, %1}, %2;" : "=r"(a), "=r"(b) : "l"(v));
    lo = __uint_as_float(a);
    hi = __uint_as_float(b);
}
// From packed (a,b) produce (a,a) and (b,b)
__device__ __forceinline__ void dup_both(ull v, ull& aa, ull& bb) {
    unsigned a, b;
    asm("mov.b64 {%0, %1}, %2;" : "=r"(a), "=r"(b) : "l"(v));
    asm("mov.b64 %0, {%1, %1};" : "=l"(aa) : "r"(a));
    asm("mov.b64 %0, {%1, %1};" : "=l"(bb) : "r"(b));
}

// ---------------- kernel A: codebook row norms + zero loss accumulator ----------------
__global__ void prep_kernel(const float* __restrict__ cb) {
    int s = threadIdx.x;
    if (s == 0) g_loss_acc = 0ull;
    if (s < SS) {
        float acc = 0.f;
#pragma unroll
        for (int c = 0; c < CC; ++c) {
            float v = cb[s * CC + c];
            acc = fmaf(v, v, acc);
        }
        g_c2[s] = acc;
    }
}

// ---------------- kernel B (fused): argmin + gather + output + loss ----------------
// Register-blocked: thread owns 2 pixels x 32 codes of packed accumulators.
// x-tile (256 px x 64 c) and cb tile (128 codes x 64 c, transposed) in dynamic
// smem. Per-code accumulation is bit-identical to the reference rounding path
// (sequential c, fma; dist = fma(acc, -2, fl(x2 + c2))). After the sweep, the
// thread gathers its winning codebook rows (L1/L2-resident) and writes the
// straight-through output, indices, and fixed-point loss partials.
//
// Output layout (fp32): [0]=loss_codebook, [1]=loss_commitment,
// [2 .. 2+NPIX) = indices (as float), [2+NPIX ..) = out (N,C,H,W)
__global__ void __launch_bounds__(TPB) argmin_fused_kernel(const float* __restrict__ x,
                                                           const float* __restrict__ cb,
                                                           float* __restrict__ out) {
    extern __shared__ __align__(16) float smem[];
    float* sx = smem;                       // [CC][PXB]
    float* scb = smem + SX_FLOATS;          // [CC][CBP] transposed tile
    float* sc2 = scb + SCB_FLOATS;          // [SS]
    __shared__ double wsum[TPB / 32];

    const int tid = threadIdx.x;
    const int pxbase = blockIdx.x * PXB;    // block never straddles image n
    const int n = pxbase >> 12;
    const int p0 = pxbase & (PP - 1);
    const float* xb = x + (size_t)n * CC * PP + p0;

    // Stage x-tile: coalesced float4 reads, contiguous smem rows
    for (int e = tid; e < CC * (PXB / 4); e += TPB) {
        int c = e >> 6;                     // PXB/4 = 64 float4 per row
        int v = e & 63;
        float4 t = *reinterpret_cast<const float4*>(xb + (size_t)c * PP + v * 4);
        *reinterpret_cast<float4*>(sx + c * PXB + v * 4) = t;
    }
    for (int e = tid; e < SS; e += TPB) sc2[e] = g_c2[e];
    __syncthreads();

    // ||x||^2 for this thread's two pixels — sequential c, fma (matches reference)
    const int px = tid * PXT;               // local pixel index (even)
    float x2a = 0.f, x2b = 0.f;
#pragma unroll
    for (int c = 0; c < CC; ++c) {
        float va = sx[c * PXB + px];
        float vb = sx[c * PXB + px + 1];
        x2a = fmaf(va, va, x2a);
        x2b = fmaf(vb, vb, x2b);
    }
    const ull x2da = pack2(x2a);
    const ull x2db = pack2(x2b);
    const ull m2d = pack2(-2.0f);

    float best0 = 3.4e38f, best1 = 3.4e38f;
    int bi0 = 0, bi1 = 0;

    for (int s0 = 0; s0 < SS; s0 += CBT) {
        __syncthreads();
        // Stage cb tile transposed: scb[c][sp] = cb[(s0+sp)][c]
        for (int e = tid; e < CBT * CC; e += TPB) {
            int sp = e >> 6;
            int c = e & 63;
            scb[c * CBP + sp] = cb[(size_t)(s0 + sp) * CC + c];
        }
        __syncthreads();

        for (int g = 0; g < CBT; g += GRP) {
            ull acc0[GRP / 2], acc1[GRP / 2];
#pragma unroll
            for (int j = 0; j < GRP / 2; ++j) { acc0[j] = 0ull; acc1[j] = 0ull; }

#pragma unroll 16
            for (int c = 0; c < CC; ++c) {
                ull xp = *reinterpret_cast<const ull*>(sx + c * PXB + px);
                ull xaa, xbb;
                dup_both(xp, xaa, xbb);
                const ulonglong2* rp =
                    reinterpret_cast<const ulonglong2*>(scb + c * CBP + g);
#pragma unroll
                for (int j4 = 0; j4 < GRP / 4; ++j4) {      // 8 x ulonglong2
                    ulonglong2 r = rp[j4];
                    acc0[2 * j4]     = fma2(xaa, r.x, acc0[2 * j4]);
                    acc0[2 * j4 + 1] = fma2(xaa, r.y, acc0[2 * j4 + 1]);
                    acc1[2 * j4]     = fma2(xbb, r.x, acc1[2 * j4]);
                    acc1[2 * j4 + 1] = fma2(xbb, r.y, acc1[2 * j4 + 1]);
                }
            }

            // dist = fl(fl(x2 + c2) - 2*cross); ascending s, strict < (first-min)
#pragma unroll
            for (int j = 0; j < GRP / 2; ++j) {
                int s = s0 + g + 2 * j;
                ull c2p = *reinterpret_cast<const ull*>(sc2 + s);
                ull d0 = fma2(acc0[j], m2d, add2(x2da, c2p));
                ull d1 = fma2(acc1[j], m2d, add2(x2db, c2p));
                float lo, hi;
                unpack2(d0, lo, hi);
                if (lo < best0) { best0 = lo; bi0 = s; }
                if (hi < best0) { best0 = hi; bi0 = s + 1; }
                unpack2(d1, lo, hi);
                if (lo < best1) { best1 = lo; bi1 = s; }
                if (hi < best1) { best1 = hi; bi1 = s + 1; }
            }
        }
    }

    // ---- fused epilogue: indices, straight-through output, loss partials ----
    out[2 + pxbase + px] = (float)bi0;
    out[2 + pxbase + px + 1] = (float)bi1;

    float* ob = out + 2 + NPIX + (size_t)n * CC * PP + p0 + px;
    const float4* crow0 = reinterpret_cast<const float4*>(cb + (size_t)bi0 * CC);
    const float4* crow1 = reinterpret_cast<const float4*>(cb + (size_t)bi1 * CC);

    float lsum = 0.f;
#pragma unroll
    for (int c4 = 0; c4 < CC / 4; ++c4) {
        float4 cv0 = crow0[c4];
        float4 cv1 = crow1[c4];
        float q0[4] = {cv0.x, cv0.y, cv0.z, cv0.w};
        float q1[4] = {cv1.x, cv1.y, cv1.z, cv1.w};
#pragma unroll
        for (int i = 0; i < 4; ++i) {
            int c = c4 * 4 + i;
            float xv0 = sx[c * PXB + px];
            float xv1 = sx[c * PXB + px + 1];
            // out = x + fl(x_q - x)  (reference rounding)
            float2 ov;
            ov.x = xv0 + (q0[i] - xv0);
            ov.y = xv1 + (q1[i] - xv1);
            *reinterpret_cast<float2*>(ob + (size_t)c * PP) = ov;
            float d0 = xv0 - q0[i];
            float d1 = xv1 - q1[i];
            lsum = fmaf(d0, d0, lsum);
            lsum = fmaf(d1, d1, lsum);
        }
    }

    // Deterministic fixed-point reduction (scale 2^32)
    double dsum = (double)lsum;
#pragma unroll
    for (int off = 16; off; off >>= 1)
        dsum += __shfl_down_sync(0xffffffffu, dsum, off);
    if ((tid & 31) == 0) wsum[tid >> 5] = dsum;
    __syncthreads();
    if (tid == 0) {
        double t = 0.0;
#pragma unroll
        for (int w = 0; w < TPB / 32; ++w) t += wsum[w];
        long long fx = __double2ll_rn(t * 4294967296.0);
        atomicAdd(&g_loss_acc, (unsigned long long)fx);
    }
}

// ---------------- kernel C: finalize losses ----------------
__global__ void finish_kernel(float* __restrict__ out) {
    double s = (double)g_loss_acc * (1.0 / 4294967296.0);
    float loss = (float)(s / (double)TOTAL);
    out[0] = loss;   // loss_codebook
    out[1] = loss;   // loss_commitment (numerically identical)
}

// ---------------- launch ----------------
extern "C" void kernel_launch(void* const* d_in, const int* in_sizes, int n_in,
                              void* d_out, int out_size) {
    const float* x = (const float*)d_in[0];
    const float* cb = (const float*)d_in[1];
    // Defensive: identify tensors by size if ordering differs
    if (n_in >= 2 && in_sizes[0] == SS * CC && in_sizes[1] == TOTAL) {
        const float* t = x; x = cb; cb = t;
    }
    float* out = (float*)d_out;

    // Unconditional (idempotent, capture-safe): no static guards allowed.
    cudaFuncSetAttribute(argmin_fused_kernel,
                         cudaFuncAttributeMaxDynamicSharedMemorySize, SMEM_BYTES);

    prep_kernel<<<1, 512>>>(cb);
    argmin_fused_kernel<<<NPIX / PXB, TPB, SMEM_BYTES>>>(x, cb, out);
    finish_kernel<<<1, 1>>>(out);
}